// round 4
// baseline (speedup 1.0000x reference)
#include <cuda_runtime.h>
#include <cuda_bf16.h>

#define MAX_B 16384
#define CHUNK 512
#define SLOT_ITEMS 32

// Scratch for per-segment sums [B, 64] floats (4 MB) — static, no allocation.
__device__ float g_scratch[MAX_B * 64];

__global__ __launch_bounds__(256)
void zero_kernel(int n4) {
    int i = blockIdx.x * blockDim.x + threadIdx.x;
    float4* s = reinterpret_cast<float4*>(g_scratch);
    if (i < n4) s[i] = make_float4(0.f, 0.f, 0.f, 0.f);
}

// Phase 1: balanced gather + segment partial sums.
// 256 threads = 16 slots x 16 lanes. Slot s owns contiguous items
// [blk*CHUNK + 32*s, +32). Lane owns one float4 of the 64-dim row.
__global__ __launch_bounds__(256)
void gather_kernel(const int* __restrict__ offsets,
                   const int* __restrict__ flat_implicit,
                   const float4* __restrict__ imp_emb4,
                   int B, int N) {
    const int t    = threadIdx.x;
    const int lane = t & 15;
    const int slot = t >> 4;

    int j = blockIdx.x * CHUNK + slot * SLOT_ITEMS;
    if (j >= N) return;
    const int run_end = min(j + SLOT_ITEMS, N);

    // Binary search: seg = last b with offsets[b] <= j
    int lo = 0, hi = B;
    while (lo < hi) {
        int mid = (lo + hi) >> 1;
        if (__ldg(&offsets[mid]) <= j) lo = mid + 1; else hi = mid;
    }
    int seg = lo - 1;

    float4 acc = make_float4(0.f, 0.f, 0.f, 0.f);

    for (;;) {
        const int nb   = (seg + 1 < B) ? __ldg(&offsets[seg + 1]) : N;
        const int stop = min(run_end, nb);

        // Hot loop: 4 independent LDG.128 in flight per thread.
        for (; j + 3 < stop; j += 4) {
            const int i0 = __ldg(&flat_implicit[j]);
            const int i1 = __ldg(&flat_implicit[j + 1]);
            const int i2 = __ldg(&flat_implicit[j + 2]);
            const int i3 = __ldg(&flat_implicit[j + 3]);
            const float4 a0 = __ldg(&imp_emb4[(size_t)i0 * 16 + lane]);
            const float4 a1 = __ldg(&imp_emb4[(size_t)i1 * 16 + lane]);
            const float4 a2 = __ldg(&imp_emb4[(size_t)i2 * 16 + lane]);
            const float4 a3 = __ldg(&imp_emb4[(size_t)i3 * 16 + lane]);
            acc.x += (a0.x + a1.x) + (a2.x + a3.x);
            acc.y += (a0.y + a1.y) + (a2.y + a3.y);
            acc.z += (a0.z + a1.z) + (a2.z + a3.z);
            acc.w += (a0.w + a1.w) + (a2.w + a3.w);
        }
        for (; j < stop; ++j) {
            const float4 a = __ldg(&imp_emb4[(size_t)__ldg(&flat_implicit[j]) * 16 + lane]);
            acc.x += a.x; acc.y += a.y; acc.z += a.z; acc.w += a.w;
        }

        // Flush this segment's partial sum.
        float* dst = g_scratch + (size_t)seg * 64 + lane * 4;
        atomicAdd(dst + 0, acc.x);
        atomicAdd(dst + 1, acc.y);
        atomicAdd(dst + 2, acc.z);
        atomicAdd(dst + 3, acc.w);

        if (stop >= run_end) break;
        acc = make_float4(0.f, 0.f, 0.f, 0.f);
        // Advance past boundary (skip empty/duplicate segments).
        seg++;
        while (seg + 1 < B && __ldg(&offsets[seg + 1]) <= j) seg++;
    }
}

// Phase 2: finalize. 16 rows per 256-thread CTA; 16 lanes per row.
__global__ __launch_bounds__(256)
void finalize_kernel(const int* __restrict__ user_ids,
                     const int* __restrict__ item_ids,
                     const int* __restrict__ offsets,
                     const float4* __restrict__ user_emb4,
                     const float4* __restrict__ item_emb4,
                     const float* __restrict__ user_bias,
                     const float* __restrict__ item_bias,
                     const float* __restrict__ global_bias,
                     float* __restrict__ out,
                     int B, int N) {
    const int t    = threadIdx.x;
    const int lane = t & 15;
    const int r    = blockIdx.x * 16 + (t >> 4);
    if (r >= B) return;

    const int start = __ldg(&offsets[r]);
    const int end   = (r + 1 < B) ? __ldg(&offsets[r + 1]) : N;
    const int len   = end - start;
    const float invnorm = (len > 0) ? rsqrtf((float)len) : 1.0f;

    const float4 sum = reinterpret_cast<const float4*>(g_scratch)[(size_t)r * 16 + lane];

    const int u  = __ldg(&user_ids[r]);
    const int it = __ldg(&item_ids[r]);
    const float4 u4 = __ldg(&user_emb4[(size_t)u * 16 + lane]);
    const float4 i4 = __ldg(&item_emb4[(size_t)it * 16 + lane]);

    float dot = (u4.x + sum.x * invnorm) * i4.x
              + (u4.y + sum.y * invnorm) * i4.y
              + (u4.z + sum.z * invnorm) * i4.z
              + (u4.w + sum.w * invnorm) * i4.w;

    // Reduce 16 lanes (width=16 keeps the two row-groups per warp separate).
    #pragma unroll
    for (int off = 8; off > 0; off >>= 1)
        dot += __shfl_down_sync(0xffffffffu, dot, off, 16);

    if (lane == 0)
        out[r] = dot + __ldg(&user_bias[u]) + __ldg(&item_bias[it]) + __ldg(&global_bias[0]);
}

extern "C" void kernel_launch(void* const* d_in, const int* in_sizes, int n_in,
                              void* d_out, int out_size) {
    const int*    user_ids      = (const int*)d_in[0];
    const int*    item_ids      = (const int*)d_in[1];
    const int*    offsets       = (const int*)d_in[2];
    const int*    flat_implicit = (const int*)d_in[3];
    const float4* user_emb4     = (const float4*)d_in[4];
    const float4* item_emb4     = (const float4*)d_in[5];
    const float4* imp_emb4      = (const float4*)d_in[6];
    const float*  user_bias     = (const float*)d_in[7];
    const float*  item_bias     = (const float*)d_in[8];
    const float*  global_bias   = (const float*)d_in[9];
    float*        out           = (float*)d_out;

    const int B = in_sizes[0];          // 16384
    const int N = in_sizes[3];          // 819200

    const int n4 = B * 16;              // float4 count in scratch
    zero_kernel<<<(n4 + 255) / 256, 256>>>(n4);

    gather_kernel<<<(N + CHUNK - 1) / CHUNK, 256>>>(offsets, flat_implicit,
                                                    imp_emb4, B, N);

    finalize_kernel<<<(B + 15) / 16, 256>>>(user_ids, item_ids, offsets,
                                            user_emb4, item_emb4,
                                            user_bias, item_bias, global_bias,
                                            out, B, N);
}